// round 15
// baseline (speedup 1.0000x reference)
#include <cuda_runtime.h>
#include <cuda_bf16.h>
#include <cstdint>

#define N_FEATS 100000
#define B_ROWS  512
#define D_DIM   512
#define C_CLS   1854
#define TOPK    10

#define KC      32
#define NCH     (D_DIM / KC)        // 16
#define NSTAGE  4
#define STAGE_BYTES 16384           // A 8K + B 8K
#define SMEM_TOTAL 69632            // max(4 stages 64K, epi 128*132*4 = 66K)
#define OFF_AH 0
#define OFF_BH 8192
#define EPI_STRIDE 132

#define SAMPLE_NT 64                // 64 * 128 = 8192 sample columns
#define SAMPLE_COLS 8192
#define NT_TOTAL ((N_FEATS + 127) / 128)   // 782
#define CAP 4096
#define MARGIN 0.2f                 // > 2x hard bf16 rounding bound (0.176)

#define HEAD_N8  (SAMPLE_COLS * D_DIM / 8)             // 524288
#define TAIL_N8  ((N_FEATS - SAMPLE_COLS) * D_DIM / 8) // 5875712
#define GEMM_BLKS 256               // 4 mg x 64 nt sample tiles

__device__ __nv_bfloat16 g_fhi[(size_t)N_FEATS * D_DIM];   // 102.4 MB
__device__ __nv_bfloat16 g_ahi[B_ROWS * D_DIM];
__device__ float g_sample[(size_t)B_ROWS * SAMPLE_COLS];   // 16 MB
__device__ float g_thresh[B_ROWS];
__device__ int   g_ccnt[B_ROWS];
__device__ int   g_cii[(size_t)B_ROWS * CAP];              // 8 MB

static __device__ __forceinline__ uint32_t smem_u32(const void* p) {
    uint32_t a;
    asm("{ .reg .u64 t; cvta.to.shared.u64 t, %1; cvt.u32.u64 %0, t; }" : "=r"(a) : "l"(p));
    return a;
}
static __device__ __forceinline__ void ldsm4(uint32_t (&r)[4], uint32_t addr) {
    asm volatile("ldmatrix.sync.aligned.m8n8.x4.shared.b16 {%0,%1,%2,%3}, [%4];"
                 : "=r"(r[0]), "=r"(r[1]), "=r"(r[2]), "=r"(r[3]) : "r"(addr));
}
static __device__ __forceinline__ void mma16816(float (&d)[4], const uint32_t (&a)[4],
                                                const uint32_t* b) {
    asm volatile(
        "mma.sync.aligned.m16n8k16.row.col.f32.bf16.bf16.f32 "
        "{%0,%1,%2,%3}, {%4,%5,%6,%7}, {%8,%9}, {%0,%1,%2,%3};"
        : "+f"(d[0]), "+f"(d[1]), "+f"(d[2]), "+f"(d[3])
        : "r"(a[0]), "r"(a[1]), "r"(a[2]), "r"(a[3]), "r"(b[0]), "r"(b[1]));
}
static __device__ __forceinline__ void cp16(uint32_t dst, const void* src, uint32_t sz) {
    asm volatile("cp.async.cg.shared.global [%0], [%1], 16, %2;"
                 :: "r"(dst), "l"(src), "r"(sz) : "memory");
}

// fp32x8 -> bf16x8 (hi) conversion of one item
static __device__ __forceinline__ void cvt8(const float* __restrict__ src,
                                            __nv_bfloat16* __restrict__ hi, int i) {
    float4 v0 = ((const float4*)src)[i * 2];
    float4 v1 = ((const float4*)src)[i * 2 + 1];
    __nv_bfloat162 h0 = __floats2bfloat162_rn(v0.x, v0.y);
    __nv_bfloat162 h1 = __floats2bfloat162_rn(v0.z, v0.w);
    __nv_bfloat162 h2 = __floats2bfloat162_rn(v1.x, v1.y);
    __nv_bfloat162 h3 = __floats2bfloat162_rn(v1.z, v1.w);
    ((uint4*)hi)[i] = make_uint4(*(uint32_t*)&h0, *(uint32_t*)&h1,
                                 *(uint32_t*)&h2, *(uint32_t*)&h3);
}

// ---------------------------------------------------------------------------
// Pre-convert kernel (used for A and for the feats head) + optional zero job
// ---------------------------------------------------------------------------
__global__ void cvt_hi_kernel(const float* __restrict__ src, __nv_bfloat16* __restrict__ hi,
                              int n8, float4* __restrict__ zdst, int zn4) {
    int i = blockIdx.x * blockDim.x + threadIdx.x;
    if (i < zn4) zdst[i] = make_float4(0.f, 0.f, 0.f, 0.f);
    if (i < n8) cvt8(src, hi, i);
}

// ---------------------------------------------------------------------------
// GEMM bodies: CTA 128x128, 2 CTAs/SM, cp.async 4-stage, single-pass bf16 HMMA
// ---------------------------------------------------------------------------
extern __shared__ char dsm[];

static __device__ __forceinline__ void issue_stage(uint32_t sbase, int c, int mg, int nt,
                                                   int tid) {
    const uint32_t stage = sbase + (c % NSTAGE) * STAGE_BYTES;
#pragma unroll
    for (int j = 0; j < 4; j++) {
        int id = tid + j * 256;     // 0..1023
        int mat = id >> 9;          // 0:Ah 1:Bh
        int rem = id & 511;
        int row = rem >> 2;
        int cc = rem & 3;
        uint32_t dst = stage + mat * 8192 + row * 64 + ((cc ^ ((row >> 1) & 3)) << 4);
        uint32_t sz = 16;
        const __nv_bfloat16* src;
        if (mat == 0) {
            src = g_ahi + (size_t)(mg * 128 + row) * D_DIM + c * KC + cc * 8;
        } else {
            int n = nt * 128 + row;
            if (n >= N_FEATS) { sz = 0; n = 0; }
            src = g_fhi + (size_t)n * D_DIM + c * KC + cc * 8;
        }
        cp16(dst, src, sz);
    }
    asm volatile("cp.async.commit_group;" ::: "memory");
}

// Mainloop + epilogue, MODE 0 = sample store, MODE 1 = filter push
template <int MODE>
static __device__ void gemm_body(int mg, int nt, int tid) {
    const int lane = tid & 31, w = tid >> 5;
    const int wm = (w >> 2) * 64;
    const int wn = (w & 3) * 32;
    const uint32_t sb = smem_u32(dsm);

    float acc[4][4][4];
#pragma unroll
    for (int i = 0; i < 4; i++)
#pragma unroll
        for (int j = 0; j < 4; j++)
#pragma unroll
            for (int q = 0; q < 4; q++) acc[i][j][q] = 0.f;

    const int rA = wm + ((lane >> 3) & 1) * 8 + (lane & 7);
    const int a_c4 = lane >> 4;
    const int rB = wn + ((lane >> 4) & 1) * 8 + (lane & 7);
    const int b_c4 = (lane >> 3) & 1;

    uint32_t aAddr[4], bAddr[2];
    int rxA[4], rxB[2];
#pragma unroll
    for (int mf = 0; mf < 4; mf++) {
        int r = rA + mf * 16;
        aAddr[mf] = r * 64;
        rxA[mf] = (r >> 1) & 3;
    }
#pragma unroll
    for (int nf2 = 0; nf2 < 2; nf2++) {
        int r = rB + nf2 * 16;
        bAddr[nf2] = r * 64;
        rxB[nf2] = (r >> 1) & 3;
    }

    issue_stage(sb, 0, mg, nt, tid);
    issue_stage(sb, 1, mg, nt, tid);
    issue_stage(sb, 2, mg, nt, tid);

#pragma unroll 1
    for (int c = 0; c < NCH; c++) {
        if (c <= NCH - 3)
            asm volatile("cp.async.wait_group 2;" ::: "memory");
        else if (c == NCH - 2)
            asm volatile("cp.async.wait_group 1;" ::: "memory");
        else
            asm volatile("cp.async.wait_group 0;" ::: "memory");
        __syncthreads();
        if (c + 3 < NCH) issue_stage(sb, c + 3, mg, nt, tid);

        const uint32_t st = sb + (c % NSTAGE) * STAGE_BYTES;
#pragma unroll
        for (int kh = 0; kh < 2; kh++) {
            uint32_t Ah[4][4], Bh[2][4];
#pragma unroll
            for (int mf = 0; mf < 4; mf++)
                ldsm4(Ah[mf], st + OFF_AH + aAddr[mf] + (((kh * 2 + a_c4) ^ rxA[mf]) << 4));
#pragma unroll
            for (int nf2 = 0; nf2 < 2; nf2++)
                ldsm4(Bh[nf2], st + OFF_BH + bAddr[nf2] + (((kh * 2 + b_c4) ^ rxB[nf2]) << 4));
#pragma unroll
            for (int mf = 0; mf < 4; mf++)
#pragma unroll
                for (int nf = 0; nf < 4; nf++)
                    mma16816(acc[mf][nf], Ah[mf], &Bh[nf >> 1][(nf & 1) * 2]);
        }
    }

    const int mrow_t = wm + (lane >> 2);
    const int ncol_t = wn + (lane & 3) * 2;

    if (MODE == 0) {
#pragma unroll
        for (int mf = 0; mf < 4; mf++) {
#pragma unroll
            for (int nf = 0; nf < 4; nf++) {
                int n = nt * 128 + ncol_t + nf * 8;
                size_t r0 = (size_t)(mg * 128 + mrow_t + mf * 16);
                *(float2*)(g_sample + r0 * SAMPLE_COLS + n) =
                    make_float2(acc[mf][nf][0], acc[mf][nf][1]);
                *(float2*)(g_sample + (r0 + 8) * SAMPLE_COLS + n) =
                    make_float2(acc[mf][nf][2], acc[mf][nf][3]);
            }
        }
    } else {
        float* epi = (float*)dsm;
        __syncthreads();   // pipeline smem is dead; safe to reuse
#pragma unroll
        for (int mf = 0; mf < 4; mf++) {
#pragma unroll
            for (int nf = 0; nf < 4; nf++) {
                int col = ncol_t + nf * 8;
                int r0 = mrow_t + mf * 16;
                *(float2*)(epi + r0 * EPI_STRIDE + col) =
                    make_float2(acc[mf][nf][0], acc[mf][nf][1]);
                *(float2*)(epi + (r0 + 8) * EPI_STRIDE + col) =
                    make_float2(acc[mf][nf][2], acc[mf][nf][3]);
            }
        }
        __syncthreads();

        const int row = tid >> 1;
        const int cbase = (tid & 1) * 64;
        const int grow = mg * 128 + row;
        const float th = g_thresh[grow];   // includes -MARGIN
        const float* rp = epi + row * EPI_STRIDE + cbase;
        const int nbase = nt * 128 + cbase;
        const int nvalid = N_FEATS - nbase;
#pragma unroll 4
        for (int i4 = 0; i4 < 16; i4++) {
            float4 v = *(const float4*)(rp + i4 * 4);
            if (v.x >= th || v.y >= th || v.z >= th || v.w >= th) {
                int j = i4 * 4;
#pragma unroll
                for (int q = 0; q < 4; q++) {
                    float val = (q == 0) ? v.x : (q == 1) ? v.y : (q == 2) ? v.z : v.w;
                    if (val >= th && j + q < nvalid) {
                        int p = atomicAdd(&g_ccnt[grow], 1);
                        if (p < CAP) g_cii[(size_t)grow * CAP + p] = nbase + j + q;
                    }
                }
            }
        }
    }
}

// Fused: blocks [0,256) sample GEMM; blocks [256,...) cvt feats tail + zero out
__global__ void __launch_bounds__(256, 2) fused_sample_cvt(const float* __restrict__ feats,
                                                           float4* __restrict__ outz,
                                                           int zn4) {
    if (blockIdx.x < GEMM_BLKS) {
        gemm_body<0>(blockIdx.x & 3, blockIdx.x >> 2, threadIdx.x);
    } else {
        int i = (blockIdx.x - GEMM_BLKS) * 256 + threadIdx.x;
        if (i < zn4) outz[i] = make_float4(0.f, 0.f, 0.f, 0.f);
        if (i < TAIL_N8)
            cvt8(feats + (size_t)SAMPLE_COLS * D_DIM,
                 g_fhi + (size_t)SAMPLE_COLS * D_DIM, i);
    }
}

// Main GEMM: non-sample tiles, filter epilogue
__global__ void __launch_bounds__(256, 2) gemm_main(void) {
    gemm_body<1>(blockIdx.x, blockIdx.y + SAMPLE_NT, threadIdx.x);
}

// ---------------------------------------------------------------------------
// Top-10 machinery (tie-break: lower index)
// ---------------------------------------------------------------------------
static __device__ __forceinline__ bool better(float v, int j, float v2, int j2) {
    return v > v2 || (v == v2 && j < j2);
}
static __device__ __forceinline__ void insert10(float (&tv)[TOPK], int (&ti)[TOPK],
                                                float v, int j) {
    if (!better(v, j, tv[TOPK - 1], ti[TOPK - 1])) return;
    bool b[TOPK];
#pragma unroll
    for (int p = 0; p < TOPK; p++) b[p] = better(v, j, tv[p], ti[p]);
#pragma unroll
    for (int p = TOPK - 1; p >= 1; p--) {
        if (b[p]) {
            if (b[p - 1]) { tv[p] = tv[p - 1]; ti[p] = ti[p - 1]; }
            else          { tv[p] = v;         ti[p] = j;         }
        }
    }
    if (b[0]) { tv[0] = v; ti[0] = j; }
}

#define TK_THREADS 256

static __device__ __forceinline__ void block_merge10(float (&tv)[TOPK], int (&ti)[TOPK],
                                                     float* sv, int* si, float* sv2,
                                                     int* si2, int tid) {
#pragma unroll
    for (int p = 0; p < TOPK; p++) { sv[tid * TOPK + p] = tv[p]; si[tid * TOPK + p] = ti[p]; }
    __syncthreads();
    if (tid < 32) {
#pragma unroll
        for (int p = 0; p < TOPK; p++) { tv[p] = -__int_as_float(0x7f800000); ti[p] = 0x7fffffff; }
        for (int c = tid * 80; c < (tid + 1) * 80; c++)
            insert10(tv, ti, sv[c], si[c]);
#pragma unroll
        for (int p = 0; p < TOPK; p++) { sv2[tid * TOPK + p] = tv[p]; si2[tid * TOPK + p] = ti[p]; }
    }
    __syncthreads();
    if (tid == 0) {
#pragma unroll
        for (int p = 0; p < TOPK; p++) { tv[p] = -__int_as_float(0x7f800000); ti[p] = 0x7fffffff; }
        for (int c = 0; c < 32 * TOPK; c++)
            insert10(tv, ti, sv2[c], si2[c]);
    }
}

// Threshold: 512 threads/row. 10th-largest of 512 per-thread fmax-maxima
// (lower bound on the sample 10th) minus MARGIN; then push sample candidates.
__global__ void __launch_bounds__(512) thresh_kernel() {
    const int row = blockIdx.x;
    const float4* s4 = (const float4*)(g_sample + (size_t)row * SAMPLE_COLS);
    const int tid = threadIdx.x;
    __shared__ float smax[512];
    __shared__ float sv2[32 * TOPK];
    __shared__ float sth;

    float4 v[4];
    float m = -__int_as_float(0x7f800000);
#pragma unroll
    for (int i = 0; i < 4; i++) {
        v[i] = s4[tid + i * 512];
        m = fmaxf(m, fmaxf(fmaxf(v[i].x, v[i].y), fmaxf(v[i].z, v[i].w)));
    }
    smax[tid] = m;
    __syncthreads();

    if (tid < 32) {
        float tv[TOPK]; int ti[TOPK];
#pragma unroll
        for (int p = 0; p < TOPK; p++) { tv[p] = -__int_as_float(0x7f800000); ti[p] = 0; }
        for (int c = tid * 16; c < (tid + 1) * 16; c++)
            insert10(tv, ti, smax[c], 0);
#pragma unroll
        for (int p = 0; p < TOPK; p++) sv2[tid * TOPK + p] = tv[p];
    }
    __syncthreads();
    if (tid == 0) {
        float tv[TOPK]; int ti[TOPK];
#pragma unroll
        for (int p = 0; p < TOPK; p++) { tv[p] = -__int_as_float(0x7f800000); ti[p] = 0; }
        for (int c = 0; c < 32 * TOPK; c++)
            insert10(tv, ti, sv2[c], 0);
        float th = tv[TOPK - 1] - MARGIN;
        g_thresh[row] = th;
        sth = th;
    }
    __syncthreads();

    const float th = sth;
#pragma unroll
    for (int i = 0; i < 4; i++) {
        if (v[i].x >= th || v[i].y >= th || v[i].z >= th || v[i].w >= th) {
            int col = (tid + i * 512) * 4;
#pragma unroll
            for (int q = 0; q < 4; q++) {
                float val = (q == 0) ? v[i].x : (q == 1) ? v[i].y : (q == 2) ? v[i].z : v[i].w;
                if (val >= th) {
                    int p = atomicAdd(&g_ccnt[row], 1);
                    if (p < CAP) g_cii[(size_t)row * CAP + p] = col + q;
                }
            }
        }
    }
}

// Rescore candidates exactly in fp32, exact top-10, scatter one-hots directly.
// Overflow rows (cnt > CAP): brute-force exact fp32.
__global__ void __launch_bounds__(TK_THREADS) rescore_select(const float* __restrict__ yp,
                                                             const float* __restrict__ feats,
                                                             const int* __restrict__ y,
                                                             float* __restrict__ out) {
    const int row = blockIdx.x;
    const int tid = threadIdx.x;
    const int lane = tid & 31, w = tid >> 5;
    const int cnt = g_ccnt[row];

    __shared__ float4 a4s[D_DIM / 4];
    __shared__ float  cvs[CAP];
    __shared__ float sv[TK_THREADS * TOPK];
    __shared__ int   si[TK_THREADS * TOPK];
    __shared__ float sv2[32 * TOPK];
    __shared__ int   si2[32 * TOPK];

    if (tid < D_DIM / 4) a4s[tid] = ((const float4*)(yp + (size_t)row * D_DIM))[tid];
    __syncthreads();

    float tv[TOPK]; int ti[TOPK];
#pragma unroll
    for (int p = 0; p < TOPK; p++) { tv[p] = -__int_as_float(0x7f800000); ti[p] = 0x7fffffff; }

    if (cnt <= CAP) {
        const int* ci = g_cii + (size_t)row * CAP;
        int c = w;
        for (; c + 8 < cnt; c += 16) {
            int i0 = ci[c], i1 = ci[c + 8];
            const float4* f0 = (const float4*)(feats + (size_t)i0 * D_DIM);
            const float4* f1 = (const float4*)(feats + (size_t)i1 * D_DIM);
            float s0 = 0.f, s1 = 0.f;
#pragma unroll
            for (int i = 0; i < 4; i++) {
                float4 b0 = f0[i * 32 + lane];
                float4 b1 = f1[i * 32 + lane];
                float4 a = a4s[i * 32 + lane];
                s0 += a.x * b0.x + a.y * b0.y + a.z * b0.z + a.w * b0.w;
                s1 += a.x * b1.x + a.y * b1.y + a.z * b1.z + a.w * b1.w;
            }
#pragma unroll
            for (int o = 16; o; o >>= 1) {
                s0 += __shfl_xor_sync(0xffffffffu, s0, o);
                s1 += __shfl_xor_sync(0xffffffffu, s1, o);
            }
            if (lane == 0) { cvs[c] = s0; cvs[c + 8] = s1; }
        }
        if (c < cnt) {
            int i0 = ci[c];
            const float4* f0 = (const float4*)(feats + (size_t)i0 * D_DIM);
            float s0 = 0.f;
#pragma unroll
            for (int i = 0; i < 4; i++) {
                float4 b0 = f0[i * 32 + lane];
                float4 a = a4s[i * 32 + lane];
                s0 += a.x * b0.x + a.y * b0.y + a.z * b0.z + a.w * b0.w;
            }
#pragma unroll
            for (int o = 16; o; o >>= 1) s0 += __shfl_xor_sync(0xffffffffu, s0, o);
            if (lane == 0) cvs[c] = s0;
        }
        __syncthreads();
        for (int k = tid; k < cnt; k += TK_THREADS)
            insert10(tv, ti, cvs[k], ci[k]);
    } else {
        for (int col = tid; col < N_FEATS; col += TK_THREADS) {
            const float4* f4 = (const float4*)(feats + (size_t)col * D_DIM);
            float s = 0.f;
#pragma unroll 8
            for (int q = 0; q < D_DIM / 4; q++) {
                float4 b = f4[q], a = a4s[q];
                s += a.x * b.x + a.y * b.y + a.z * b.z + a.w * b.w;
            }
            insert10(tv, ti, s, col);
        }
    }
    block_merge10(tv, ti, sv, si, sv2, si2, tid);
    if (tid == 0) {
#pragma unroll
        for (int p = 0; p < TOPK; p++)
            out[(size_t)row * C_CLS + y[ti[p]]] = 1.0f;
    }
}

// ---------------------------------------------------------------------------
extern "C" void kernel_launch(void* const* d_in, const int* in_sizes, int n_in,
                              void* d_out, int out_size) {
    const float* y_pred = (const float*)d_in[0];
    const float* feats  = (const float*)d_in[1];
    const int*   y      = (const int*)d_in[2];
    float* out = (float*)d_out;

    static __nv_bfloat16 *p_fhi = nullptr, *p_ahi = nullptr;
    static float4* p_cnt4 = nullptr;
    if (!p_fhi) {
        cudaGetSymbolAddress((void**)&p_fhi, g_fhi);
        cudaGetSymbolAddress((void**)&p_ahi, g_ahi);
        cudaGetSymbolAddress((void**)&p_cnt4, g_ccnt);
        cudaFuncSetAttribute(fused_sample_cvt, cudaFuncAttributeMaxDynamicSharedMemorySize,
                             SMEM_TOTAL);
        cudaFuncSetAttribute(gemm_main, cudaFuncAttributeMaxDynamicSharedMemorySize,
                             SMEM_TOTAL);
    }

    // 1. cvt A (also zeroes g_ccnt: 512 ints = 128 float4)
    cvt_hi_kernel<<<B_ROWS * D_DIM / 8 / 256, 256>>>(y_pred, p_ahi, B_ROWS * D_DIM / 8,
                                                     p_cnt4, B_ROWS / 4);
    // 2. cvt feats head (sample region rows 0..8191)
    cvt_hi_kernel<<<HEAD_N8 / 256, 256>>>(feats, p_fhi, HEAD_N8, nullptr, 0);

    // 3. Fused: sample GEMM (blocks 0..255) || cvt feats tail + zero out
    int tail_blks = (TAIL_N8 + 255) / 256;
    fused_sample_cvt<<<GEMM_BLKS + tail_blks, 256, SMEM_TOTAL>>>(feats, (float4*)out,
                                                                 out_size / 4);

    // 4. Threshold + sample-region candidate push
    thresh_kernel<<<B_ROWS, 512>>>();

    // 5. Main GEMM: remaining 718 tiles, fused candidate filter
    gemm_main<<<dim3(4, NT_TOTAL - SAMPLE_NT), 256, SMEM_TOTAL>>>();

    // 6. Exact rescore + direct one-hot scatter
    rescore_select<<<B_ROWS, TK_THREADS>>>(y_pred, feats, y, out);
}

// round 16
// speedup vs baseline: 1.0624x; 1.0624x over previous
#include <cuda_runtime.h>
#include <cuda_bf16.h>
#include <cstdint>

#define N_FEATS 100000
#define B_ROWS  512
#define D_DIM   512
#define C_CLS   1854
#define TOPK    10

#define KC      32
#define NCH     (D_DIM / KC)        // 16
#define NSTAGE  4
#define STAGE_BYTES 16384           // A 8K + B 8K
#define SMEM_TOTAL 69632            // max(4 stages 64K, epi 128*132*4 = 66K)
#define OFF_AH 0
#define OFF_BH 8192
#define EPI_STRIDE 132

#define SAMPLE_NT 64                // 64 * 128 = 8192 sample columns
#define SAMPLE_COLS 8192
#define NT_TOTAL ((N_FEATS + 127) / 128)   // 782
#define CAP 4096
#define MARGIN 0.2f                 // > 2x hard bf16 rounding bound (0.176)

#define HEAD_N8  (SAMPLE_COLS * D_DIM / 8)             // 524288
#define TAIL_N8  ((N_FEATS - SAMPLE_COLS) * D_DIM / 8) // 5875712

__device__ __nv_bfloat16 g_fhi[(size_t)N_FEATS * D_DIM];   // 102.4 MB
__device__ __nv_bfloat16 g_ahi[B_ROWS * D_DIM];
__device__ float g_sample[(size_t)B_ROWS * SAMPLE_COLS];   // 16 MB
__device__ float g_thresh[B_ROWS];
__device__ int   g_ccnt[B_ROWS];
__device__ int   g_cii[(size_t)B_ROWS * CAP];              // 8 MB

static __device__ __forceinline__ uint32_t smem_u32(const void* p) {
    uint32_t a;
    asm("{ .reg .u64 t; cvta.to.shared.u64 t, %1; cvt.u32.u64 %0, t; }" : "=r"(a) : "l"(p));
    return a;
}
static __device__ __forceinline__ void ldsm4(uint32_t (&r)[4], uint32_t addr) {
    asm volatile("ldmatrix.sync.aligned.m8n8.x4.shared.b16 {%0,%1,%2,%3}, [%4];"
                 : "=r"(r[0]), "=r"(r[1]), "=r"(r[2]), "=r"(r[3]) : "r"(addr));
}
static __device__ __forceinline__ void mma16816(float (&d)[4], const uint32_t (&a)[4],
                                                const uint32_t* b) {
    asm volatile(
        "mma.sync.aligned.m16n8k16.row.col.f32.bf16.bf16.f32 "
        "{%0,%1,%2,%3}, {%4,%5,%6,%7}, {%8,%9}, {%0,%1,%2,%3};"
        : "+f"(d[0]), "+f"(d[1]), "+f"(d[2]), "+f"(d[3])
        : "r"(a[0]), "r"(a[1]), "r"(a[2]), "r"(a[3]), "r"(b[0]), "r"(b[1]));
}
static __device__ __forceinline__ void cp16(uint32_t dst, const void* src, uint32_t sz) {
    asm volatile("cp.async.cg.shared.global [%0], [%1], 16, %2;"
                 :: "r"(dst), "l"(src), "r"(sz) : "memory");
}

// fp32x8 -> bf16x8 (hi) conversion of one item
static __device__ __forceinline__ void cvt8(const float* __restrict__ src,
                                            __nv_bfloat16* __restrict__ hi, int i) {
    float4 v0 = ((const float4*)src)[i * 2];
    float4 v1 = ((const float4*)src)[i * 2 + 1];
    __nv_bfloat162 h0 = __floats2bfloat162_rn(v0.x, v0.y);
    __nv_bfloat162 h1 = __floats2bfloat162_rn(v0.z, v0.w);
    __nv_bfloat162 h2 = __floats2bfloat162_rn(v1.x, v1.y);
    __nv_bfloat162 h3 = __floats2bfloat162_rn(v1.z, v1.w);
    ((uint4*)hi)[i] = make_uint4(*(uint32_t*)&h0, *(uint32_t*)&h1,
                                 *(uint32_t*)&h2, *(uint32_t*)&h3);
}

// ---------------------------------------------------------------------------
// Pre-convert kernel (A and feats head) + optional zero job
// ---------------------------------------------------------------------------
__global__ void cvt_hi_kernel(const float* __restrict__ src, __nv_bfloat16* __restrict__ hi,
                              int n8, float4* __restrict__ zdst, int zn4) {
    int i = blockIdx.x * blockDim.x + threadIdx.x;
    if (i < zn4) zdst[i] = make_float4(0.f, 0.f, 0.f, 0.f);
    if (i < n8) cvt8(src, hi, i);
}

// ---------------------------------------------------------------------------
// GEMM: CTA 128x128, 2 CTAs/SM, cp.async 4-stage, single-pass bf16 HMMA
// MODE 0: store sims to g_sample, then cvt feats tail (grid-stride)
// MODE 1: smem-staged filter, push indices (skips the sample tiles)
// ---------------------------------------------------------------------------
extern __shared__ char dsm[];

static __device__ __forceinline__ void issue_stage(uint32_t sbase, int c, int mg, int nt,
                                                   int tid) {
    const uint32_t stage = sbase + (c % NSTAGE) * STAGE_BYTES;
#pragma unroll
    for (int j = 0; j < 4; j++) {
        int id = tid + j * 256;     // 0..1023
        int mat = id >> 9;          // 0:Ah 1:Bh
        int rem = id & 511;
        int row = rem >> 2;
        int cc = rem & 3;
        uint32_t dst = stage + mat * 8192 + row * 64 + ((cc ^ ((row >> 1) & 3)) << 4);
        uint32_t sz = 16;
        const __nv_bfloat16* src;
        if (mat == 0) {
            src = g_ahi + (size_t)(mg * 128 + row) * D_DIM + c * KC + cc * 8;
        } else {
            int n = nt * 128 + row;
            if (n >= N_FEATS) { sz = 0; n = 0; }
            src = g_fhi + (size_t)n * D_DIM + c * KC + cc * 8;
        }
        cp16(dst, src, sz);
    }
    asm volatile("cp.async.commit_group;" ::: "memory");
}

template <int MODE>
__global__ void __launch_bounds__(256, 2) gemm_hmma(const float* __restrict__ feats) {
    const int mg = blockIdx.x;
    const int nt = (MODE == 0) ? blockIdx.y : blockIdx.y + SAMPLE_NT;
    const int tid = threadIdx.x;
    const int lane = tid & 31, w = tid >> 5;
    const int wm = (w >> 2) * 64;
    const int wn = (w & 3) * 32;
    const uint32_t sb = smem_u32(dsm);

    float acc[4][4][4];
#pragma unroll
    for (int i = 0; i < 4; i++)
#pragma unroll
        for (int j = 0; j < 4; j++)
#pragma unroll
            for (int q = 0; q < 4; q++) acc[i][j][q] = 0.f;

    const int rA = wm + ((lane >> 3) & 1) * 8 + (lane & 7);
    const int a_c4 = lane >> 4;
    const int rB = wn + ((lane >> 4) & 1) * 8 + (lane & 7);
    const int b_c4 = (lane >> 3) & 1;

    uint32_t aAddr[4], bAddr[2];
    int rxA[4], rxB[2];
#pragma unroll
    for (int mf = 0; mf < 4; mf++) {
        int r = rA + mf * 16;
        aAddr[mf] = r * 64;
        rxA[mf] = (r >> 1) & 3;
    }
#pragma unroll
    for (int nf2 = 0; nf2 < 2; nf2++) {
        int r = rB + nf2 * 16;
        bAddr[nf2] = r * 64;
        rxB[nf2] = (r >> 1) & 3;
    }

    issue_stage(sb, 0, mg, nt, tid);
    issue_stage(sb, 1, mg, nt, tid);
    issue_stage(sb, 2, mg, nt, tid);

#pragma unroll 1
    for (int c = 0; c < NCH; c++) {
        if (c <= NCH - 3)
            asm volatile("cp.async.wait_group 2;" ::: "memory");
        else if (c == NCH - 2)
            asm volatile("cp.async.wait_group 1;" ::: "memory");
        else
            asm volatile("cp.async.wait_group 0;" ::: "memory");
        __syncthreads();
        if (c + 3 < NCH) issue_stage(sb, c + 3, mg, nt, tid);

        const uint32_t st = sb + (c % NSTAGE) * STAGE_BYTES;
#pragma unroll
        for (int kh = 0; kh < 2; kh++) {
            uint32_t Ah[4][4], Bh[2][4];
#pragma unroll
            for (int mf = 0; mf < 4; mf++)
                ldsm4(Ah[mf], st + OFF_AH + aAddr[mf] + (((kh * 2 + a_c4) ^ rxA[mf]) << 4));
#pragma unroll
            for (int nf2 = 0; nf2 < 2; nf2++)
                ldsm4(Bh[nf2], st + OFF_BH + bAddr[nf2] + (((kh * 2 + b_c4) ^ rxB[nf2]) << 4));
#pragma unroll
            for (int mf = 0; mf < 4; mf++)
#pragma unroll
                for (int nf = 0; nf < 4; nf++)
                    mma16816(acc[mf][nf], Ah[mf], &Bh[nf >> 1][(nf & 1) * 2]);
        }
    }

    const int mrow_t = wm + (lane >> 2);
    const int ncol_t = wn + (lane & 3) * 2;

    if (MODE == 0) {
#pragma unroll
        for (int mf = 0; mf < 4; mf++) {
#pragma unroll
            for (int nf = 0; nf < 4; nf++) {
                int n = nt * 128 + ncol_t + nf * 8;
                size_t r0 = (size_t)(mg * 128 + mrow_t + mf * 16);
                *(float2*)(g_sample + r0 * SAMPLE_COLS + n) =
                    make_float2(acc[mf][nf][0], acc[mf][nf][1]);
                *(float2*)(g_sample + (r0 + 8) * SAMPLE_COLS + n) =
                    make_float2(acc[mf][nf][2], acc[mf][nf][3]);
            }
        }
        // cvt feats tail: 256 blocks x 256 threads grid-stride over 5.88M items
        const float* ftail = feats + (size_t)SAMPLE_COLS * D_DIM;
        __nv_bfloat16* htail = g_fhi + (size_t)SAMPLE_COLS * D_DIM;
        const int blk = mg + nt * 4;          // 0..255
#pragma unroll 1
        for (int i = blk * 256 + tid; i < TAIL_N8; i += 256 * 256)
            cvt8(ftail, htail, i);
    } else {
        float* epi = (float*)dsm;
        __syncthreads();   // pipeline smem is dead; safe to reuse
#pragma unroll
        for (int mf = 0; mf < 4; mf++) {
#pragma unroll
            for (int nf = 0; nf < 4; nf++) {
                int col = ncol_t + nf * 8;
                int r0 = mrow_t + mf * 16;
                *(float2*)(epi + r0 * EPI_STRIDE + col) =
                    make_float2(acc[mf][nf][0], acc[mf][nf][1]);
                *(float2*)(epi + (r0 + 8) * EPI_STRIDE + col) =
                    make_float2(acc[mf][nf][2], acc[mf][nf][3]);
            }
        }
        __syncthreads();

        const int row = tid >> 1;
        const int cbase = (tid & 1) * 64;
        const int grow = mg * 128 + row;
        const float th = g_thresh[grow];   // includes -MARGIN
        const float* rp = epi + row * EPI_STRIDE + cbase;
        const int nbase = nt * 128 + cbase;
        const int nvalid = N_FEATS - nbase;
#pragma unroll 4
        for (int i4 = 0; i4 < 16; i4++) {
            float4 v = *(const float4*)(rp + i4 * 4);
            if (v.x >= th || v.y >= th || v.z >= th || v.w >= th) {
                int j = i4 * 4;
#pragma unroll
                for (int q = 0; q < 4; q++) {
                    float val = (q == 0) ? v.x : (q == 1) ? v.y : (q == 2) ? v.z : v.w;
                    if (val >= th && j + q < nvalid) {
                        int p = atomicAdd(&g_ccnt[grow], 1);
                        if (p < CAP) g_cii[(size_t)grow * CAP + p] = nbase + j + q;
                    }
                }
            }
        }
    }
}

// ---------------------------------------------------------------------------
// Top-10 machinery (tie-break: lower index)
// ---------------------------------------------------------------------------
static __device__ __forceinline__ bool better(float v, int j, float v2, int j2) {
    return v > v2 || (v == v2 && j < j2);
}
static __device__ __forceinline__ void insert10(float (&tv)[TOPK], int (&ti)[TOPK],
                                                float v, int j) {
    if (!better(v, j, tv[TOPK - 1], ti[TOPK - 1])) return;
    bool b[TOPK];
#pragma unroll
    for (int p = 0; p < TOPK; p++) b[p] = better(v, j, tv[p], ti[p]);
#pragma unroll
    for (int p = TOPK - 1; p >= 1; p--) {
        if (b[p]) {
            if (b[p - 1]) { tv[p] = tv[p - 1]; ti[p] = ti[p - 1]; }
            else          { tv[p] = v;         ti[p] = j;         }
        }
    }
    if (b[0]) { tv[0] = v; ti[0] = j; }
}

#define TK_THREADS 256

static __device__ __forceinline__ void block_merge10(float (&tv)[TOPK], int (&ti)[TOPK],
                                                     float* sv, int* si, float* sv2,
                                                     int* si2, int tid) {
#pragma unroll
    for (int p = 0; p < TOPK; p++) { sv[tid * TOPK + p] = tv[p]; si[tid * TOPK + p] = ti[p]; }
    __syncthreads();
    if (tid < 32) {
#pragma unroll
        for (int p = 0; p < TOPK; p++) { tv[p] = -__int_as_float(0x7f800000); ti[p] = 0x7fffffff; }
        for (int c = tid * 80; c < (tid + 1) * 80; c++)
            insert10(tv, ti, sv[c], si[c]);
#pragma unroll
        for (int p = 0; p < TOPK; p++) { sv2[tid * TOPK + p] = tv[p]; si2[tid * TOPK + p] = ti[p]; }
    }
    __syncthreads();
    if (tid == 0) {
#pragma unroll
        for (int p = 0; p < TOPK; p++) { tv[p] = -__int_as_float(0x7f800000); ti[p] = 0x7fffffff; }
        for (int c = 0; c < 32 * TOPK; c++)
            insert10(tv, ti, sv2[c], si2[c]);
    }
}

// Threshold: 10th-largest of 256 per-thread fmax-maxima (lower bound on the
// sample 10th) minus MARGIN; then push sample-region candidates from registers.
__global__ void __launch_bounds__(TK_THREADS) thresh_kernel() {
    const int row = blockIdx.x;
    const float4* s4 = (const float4*)(g_sample + (size_t)row * SAMPLE_COLS);
    const int tid = threadIdx.x;
    __shared__ float smax[TK_THREADS];
    __shared__ float sv2[32 * TOPK];
    __shared__ float sth;

    float4 v[8];
    float m = -__int_as_float(0x7f800000);
#pragma unroll
    for (int i = 0; i < 8; i++) {
        v[i] = s4[tid + i * TK_THREADS];
        m = fmaxf(m, fmaxf(fmaxf(v[i].x, v[i].y), fmaxf(v[i].z, v[i].w)));
    }
    smax[tid] = m;
    __syncthreads();

    if (tid < 32) {
        float tv[TOPK]; int ti[TOPK];
#pragma unroll
        for (int p = 0; p < TOPK; p++) { tv[p] = -__int_as_float(0x7f800000); ti[p] = 0; }
        for (int c = tid * 8; c < (tid + 1) * 8; c++)
            insert10(tv, ti, smax[c], 0);
#pragma unroll
        for (int p = 0; p < TOPK; p++) sv2[tid * TOPK + p] = tv[p];
    }
    __syncthreads();
    if (tid == 0) {
        float tv[TOPK]; int ti[TOPK];
#pragma unroll
        for (int p = 0; p < TOPK; p++) { tv[p] = -__int_as_float(0x7f800000); ti[p] = 0; }
        for (int c = 0; c < 32 * TOPK; c++)
            insert10(tv, ti, sv2[c], 0);
        float th = tv[TOPK - 1] - MARGIN;
        g_thresh[row] = th;
        sth = th;
    }
    __syncthreads();

    // Push sample-region candidates (values still in registers)
    const float th = sth;
#pragma unroll
    for (int i = 0; i < 8; i++) {
        if (v[i].x >= th || v[i].y >= th || v[i].z >= th || v[i].w >= th) {
            int col = (tid + i * TK_THREADS) * 4;
#pragma unroll
            for (int q = 0; q < 4; q++) {
                float val = (q == 0) ? v[i].x : (q == 1) ? v[i].y : (q == 2) ? v[i].z : v[i].w;
                if (val >= th) {
                    int p = atomicAdd(&g_ccnt[row], 1);
                    if (p < CAP) g_cii[(size_t)row * CAP + p] = col + q;
                }
            }
        }
    }
}

// Rescore candidates exactly in fp32, exact top-10, scatter one-hots directly.
// Overflow rows (cnt > CAP): brute-force exact fp32.
__global__ void __launch_bounds__(TK_THREADS) rescore_select(const float* __restrict__ yp,
                                                             const float* __restrict__ feats,
                                                             const int* __restrict__ y,
                                                             float* __restrict__ out) {
    const int row = blockIdx.x;
    const int tid = threadIdx.x;
    const int lane = tid & 31, w = tid >> 5;
    const int cnt = g_ccnt[row];

    __shared__ float4 a4s[D_DIM / 4];
    __shared__ float  cvs[CAP];
    __shared__ float sv[TK_THREADS * TOPK];
    __shared__ int   si[TK_THREADS * TOPK];
    __shared__ float sv2[32 * TOPK];
    __shared__ int   si2[32 * TOPK];

    if (tid < D_DIM / 4) a4s[tid] = ((const float4*)(yp + (size_t)row * D_DIM))[tid];
    __syncthreads();

    float tv[TOPK]; int ti[TOPK];
#pragma unroll
    for (int p = 0; p < TOPK; p++) { tv[p] = -__int_as_float(0x7f800000); ti[p] = 0x7fffffff; }

    if (cnt <= CAP) {
        const int* ci = g_cii + (size_t)row * CAP;
        int c = w;
        for (; c + 8 < cnt; c += 16) {
            int i0 = ci[c], i1 = ci[c + 8];
            const float4* f0 = (const float4*)(feats + (size_t)i0 * D_DIM);
            const float4* f1 = (const float4*)(feats + (size_t)i1 * D_DIM);
            float s0 = 0.f, s1 = 0.f;
#pragma unroll
            for (int i = 0; i < 4; i++) {
                float4 b0 = f0[i * 32 + lane];
                float4 b1 = f1[i * 32 + lane];
                float4 a = a4s[i * 32 + lane];
                s0 += a.x * b0.x + a.y * b0.y + a.z * b0.z + a.w * b0.w;
                s1 += a.x * b1.x + a.y * b1.y + a.z * b1.z + a.w * b1.w;
            }
#pragma unroll
            for (int o = 16; o; o >>= 1) {
                s0 += __shfl_xor_sync(0xffffffffu, s0, o);
                s1 += __shfl_xor_sync(0xffffffffu, s1, o);
            }
            if (lane == 0) { cvs[c] = s0; cvs[c + 8] = s1; }
        }
        if (c < cnt) {
            int i0 = ci[c];
            const float4* f0 = (const float4*)(feats + (size_t)i0 * D_DIM);
            float s0 = 0.f;
#pragma unroll
            for (int i = 0; i < 4; i++) {
                float4 b0 = f0[i * 32 + lane];
                float4 a = a4s[i * 32 + lane];
                s0 += a.x * b0.x + a.y * b0.y + a.z * b0.z + a.w * b0.w;
            }
#pragma unroll
            for (int o = 16; o; o >>= 1) s0 += __shfl_xor_sync(0xffffffffu, s0, o);
            if (lane == 0) cvs[c] = s0;
        }
        __syncthreads();
        for (int k = tid; k < cnt; k += TK_THREADS)
            insert10(tv, ti, cvs[k], ci[k]);
    } else {
        for (int col = tid; col < N_FEATS; col += TK_THREADS) {
            const float4* f4 = (const float4*)(feats + (size_t)col * D_DIM);
            float s = 0.f;
#pragma unroll 8
            for (int q = 0; q < D_DIM / 4; q++) {
                float4 b = f4[q], a = a4s[q];
                s += a.x * b.x + a.y * b.y + a.z * b.z + a.w * b.w;
            }
            insert10(tv, ti, s, col);
        }
    }
    block_merge10(tv, ti, sv, si, sv2, si2, tid);
    if (tid == 0) {
#pragma unroll
        for (int p = 0; p < TOPK; p++)
            out[(size_t)row * C_CLS + y[ti[p]]] = 1.0f;
    }
}

// ---------------------------------------------------------------------------
extern "C" void kernel_launch(void* const* d_in, const int* in_sizes, int n_in,
                              void* d_out, int out_size) {
    const float* y_pred = (const float*)d_in[0];
    const float* feats  = (const float*)d_in[1];
    const int*   y      = (const int*)d_in[2];
    float* out = (float*)d_out;

    static __nv_bfloat16 *p_fhi = nullptr, *p_ahi = nullptr;
    static float4* p_cnt4 = nullptr;
    if (!p_fhi) {
        cudaGetSymbolAddress((void**)&p_fhi, g_fhi);
        cudaGetSymbolAddress((void**)&p_ahi, g_ahi);
        cudaGetSymbolAddress((void**)&p_cnt4, g_ccnt);
        cudaFuncSetAttribute(gemm_hmma<0>, cudaFuncAttributeMaxDynamicSharedMemorySize,
                             SMEM_TOTAL);
        cudaFuncSetAttribute(gemm_hmma<1>, cudaFuncAttributeMaxDynamicSharedMemorySize,
                             SMEM_TOTAL);
    }

    // 1. cvt A (also zeroes g_ccnt: 512 ints = 128 float4)
    cvt_hi_kernel<<<B_ROWS * D_DIM / 8 / 256, 256>>>(y_pred, p_ahi, B_ROWS * D_DIM / 8,
                                                     p_cnt4, B_ROWS / 4);
    // 2. cvt feats head (rows 0..8191) + zero output buffer
    cvt_hi_kernel<<<HEAD_N8 / 256, 256>>>(feats, p_fhi, HEAD_N8, (float4*)out,
                                          out_size / 4);

    // 3. Sample GEMM (with fused feats-tail cvt after epilogue)
    gemm_hmma<0><<<dim3(4, SAMPLE_NT), 256, SMEM_TOTAL>>>(feats);

    // 4. Threshold + sample-region candidate push
    thresh_kernel<<<B_ROWS, TK_THREADS>>>();

    // 5. Main GEMM: remaining 718 tiles, fused candidate filter
    gemm_hmma<1><<<dim3(4, NT_TOTAL - SAMPLE_NT), 256, SMEM_TOTAL>>>(feats);

    // 6. Exact rescore + direct one-hot scatter
    rescore_select<<<B_ROWS, TK_THREADS>>>(y_pred, feats, y, out);
}

// round 17
// speedup vs baseline: 1.1641x; 1.0958x over previous
#include <cuda_runtime.h>
#include <cuda_bf16.h>
#include <cstdint>

#define N_FEATS 100000
#define B_ROWS  512
#define D_DIM   512
#define C_CLS   1854
#define TOPK    10

#define KC      32
#define NCH     (D_DIM / KC)        // 16
#define NSTAGE  4
#define STAGE_BYTES 16384           // A 8K + B 8K
#define SMEM_TOTAL 69632            // max(4 stages 64K, epi 128*132*4 = 66K)
#define OFF_AH 0
#define OFF_BH 8192
#define EPI_STRIDE 132

#define SAMPLE_NT 64                // 64 * 128 = 8192 sample columns
#define SAMPLE_COLS 8192
#define NT_TOTAL ((N_FEATS + 127) / 128)   // 782
#define CAP 4096
#define MARGIN 0.2f                 // > 2x hard bf16 rounding bound (0.176)

__device__ __nv_bfloat16 g_fhi[(size_t)N_FEATS * D_DIM];   // 102.4 MB
__device__ __nv_bfloat16 g_ahi[B_ROWS * D_DIM];
__device__ float g_sample[(size_t)B_ROWS * SAMPLE_COLS];   // 16 MB
__device__ float g_thresh[B_ROWS];
__device__ int   g_ccnt[B_ROWS];
__device__ int   g_cii[(size_t)B_ROWS * CAP];              // 8 MB

static __device__ __forceinline__ uint32_t smem_u32(const void* p) {
    uint32_t a;
    asm("{ .reg .u64 t; cvta.to.shared.u64 t, %1; cvt.u32.u64 %0, t; }" : "=r"(a) : "l"(p));
    return a;
}
static __device__ __forceinline__ void ldsm4(uint32_t (&r)[4], uint32_t addr) {
    asm volatile("ldmatrix.sync.aligned.m8n8.x4.shared.b16 {%0,%1,%2,%3}, [%4];"
                 : "=r"(r[0]), "=r"(r[1]), "=r"(r[2]), "=r"(r[3]) : "r"(addr));
}
static __device__ __forceinline__ void mma16816(float (&d)[4], const uint32_t (&a)[4],
                                                const uint32_t* b) {
    asm volatile(
        "mma.sync.aligned.m16n8k16.row.col.f32.bf16.bf16.f32 "
        "{%0,%1,%2,%3}, {%4,%5,%6,%7}, {%8,%9}, {%0,%1,%2,%3};"
        : "+f"(d[0]), "+f"(d[1]), "+f"(d[2]), "+f"(d[3])
        : "r"(a[0]), "r"(a[1]), "r"(a[2]), "r"(a[3]), "r"(b[0]), "r"(b[1]));
}
static __device__ __forceinline__ void cp16(uint32_t dst, const void* src, uint32_t sz) {
    asm volatile("cp.async.cg.shared.global [%0], [%1], 16, %2;"
                 :: "r"(dst), "l"(src), "r"(sz) : "memory");
}

// ---------------------------------------------------------------------------
// Pre-convert fp32 -> bf16 (hi only) + fold in an independent zeroing job
// ---------------------------------------------------------------------------
__global__ void cvt_hi_kernel(const float* __restrict__ src, __nv_bfloat16* __restrict__ hi,
                              int n8, float4* __restrict__ zdst, int zn4) {
    int i = blockIdx.x * blockDim.x + threadIdx.x;
    if (i < zn4) zdst[i] = make_float4(0.f, 0.f, 0.f, 0.f);
    if (i >= n8) return;
    float4 v0 = ((const float4*)src)[i * 2];
    float4 v1 = ((const float4*)src)[i * 2 + 1];
    __nv_bfloat162 h0 = __floats2bfloat162_rn(v0.x, v0.y);
    __nv_bfloat162 h1 = __floats2bfloat162_rn(v0.z, v0.w);
    __nv_bfloat162 h2 = __floats2bfloat162_rn(v1.x, v1.y);
    __nv_bfloat162 h3 = __floats2bfloat162_rn(v1.z, v1.w);
    ((uint4*)hi)[i] = make_uint4(*(uint32_t*)&h0, *(uint32_t*)&h1,
                                 *(uint32_t*)&h2, *(uint32_t*)&h3);
}

// ---------------------------------------------------------------------------
// GEMM: CTA 128x128, 2 CTAs/SM, cp.async 4-stage, single-pass bf16 HMMA
// MODE 0: store sims to g_sample   MODE 1: smem-staged filter, push indices
// (R14 configuration; MODE 1 skips the SAMPLE_NT sample tiles)
// ---------------------------------------------------------------------------
extern __shared__ char dsm[];

static __device__ __forceinline__ void issue_stage(uint32_t sbase, int c, int mg, int nt,
                                                   int tid) {
    const uint32_t stage = sbase + (c % NSTAGE) * STAGE_BYTES;
#pragma unroll
    for (int j = 0; j < 4; j++) {
        int id = tid + j * 256;     // 0..1023
        int mat = id >> 9;          // 0:Ah 1:Bh
        int rem = id & 511;
        int row = rem >> 2;
        int cc = rem & 3;
        uint32_t dst = stage + mat * 8192 + row * 64 + ((cc ^ ((row >> 1) & 3)) << 4);
        uint32_t sz = 16;
        const __nv_bfloat16* src;
        if (mat == 0) {
            src = g_ahi + (size_t)(mg * 128 + row) * D_DIM + c * KC + cc * 8;
        } else {
            int n = nt * 128 + row;
            if (n >= N_FEATS) { sz = 0; n = 0; }
            src = g_fhi + (size_t)n * D_DIM + c * KC + cc * 8;
        }
        cp16(dst, src, sz);
    }
    asm volatile("cp.async.commit_group;" ::: "memory");
}

template <int MODE>
__global__ void __launch_bounds__(256, 2) gemm_hmma(void) {
    const int mg = blockIdx.x;
    const int nt = (MODE == 0) ? blockIdx.y : blockIdx.y + SAMPLE_NT;
    const int tid = threadIdx.x;
    const int lane = tid & 31, w = tid >> 5;
    const int wm = (w >> 2) * 64;
    const int wn = (w & 3) * 32;
    const uint32_t sb = smem_u32(dsm);

    float acc[4][4][4];
#pragma unroll
    for (int i = 0; i < 4; i++)
#pragma unroll
        for (int j = 0; j < 4; j++)
#pragma unroll
            for (int q = 0; q < 4; q++) acc[i][j][q] = 0.f;

    const int rA = wm + ((lane >> 3) & 1) * 8 + (lane & 7);
    const int a_c4 = lane >> 4;
    const int rB = wn + ((lane >> 4) & 1) * 8 + (lane & 7);
    const int b_c4 = (lane >> 3) & 1;

    uint32_t aAddr[4], bAddr[2];
    int rxA[4], rxB[2];
#pragma unroll
    for (int mf = 0; mf < 4; mf++) {
        int r = rA + mf * 16;
        aAddr[mf] = r * 64;
        rxA[mf] = (r >> 1) & 3;
    }
#pragma unroll
    for (int nf2 = 0; nf2 < 2; nf2++) {
        int r = rB + nf2 * 16;
        bAddr[nf2] = r * 64;
        rxB[nf2] = (r >> 1) & 3;
    }

    issue_stage(sb, 0, mg, nt, tid);
    issue_stage(sb, 1, mg, nt, tid);
    issue_stage(sb, 2, mg, nt, tid);

#pragma unroll 1
    for (int c = 0; c < NCH; c++) {
        if (c <= NCH - 3)
            asm volatile("cp.async.wait_group 2;" ::: "memory");
        else if (c == NCH - 2)
            asm volatile("cp.async.wait_group 1;" ::: "memory");
        else
            asm volatile("cp.async.wait_group 0;" ::: "memory");
        __syncthreads();
        if (c + 3 < NCH) issue_stage(sb, c + 3, mg, nt, tid);

        const uint32_t st = sb + (c % NSTAGE) * STAGE_BYTES;
#pragma unroll
        for (int kh = 0; kh < 2; kh++) {
            uint32_t Ah[4][4], Bh[2][4];
#pragma unroll
            for (int mf = 0; mf < 4; mf++)
                ldsm4(Ah[mf], st + OFF_AH + aAddr[mf] + (((kh * 2 + a_c4) ^ rxA[mf]) << 4));
#pragma unroll
            for (int nf2 = 0; nf2 < 2; nf2++)
                ldsm4(Bh[nf2], st + OFF_BH + bAddr[nf2] + (((kh * 2 + b_c4) ^ rxB[nf2]) << 4));
#pragma unroll
            for (int mf = 0; mf < 4; mf++)
#pragma unroll
                for (int nf = 0; nf < 4; nf++)
                    mma16816(acc[mf][nf], Ah[mf], &Bh[nf >> 1][(nf & 1) * 2]);
        }
    }

    const int mrow_t = wm + (lane >> 2);
    const int ncol_t = wn + (lane & 3) * 2;

    if (MODE == 0) {
#pragma unroll
        for (int mf = 0; mf < 4; mf++) {
#pragma unroll
            for (int nf = 0; nf < 4; nf++) {
                int n = nt * 128 + ncol_t + nf * 8;
                size_t r0 = (size_t)(mg * 128 + mrow_t + mf * 16);
                *(float2*)(g_sample + r0 * SAMPLE_COLS + n) =
                    make_float2(acc[mf][nf][0], acc[mf][nf][1]);
                *(float2*)(g_sample + (r0 + 8) * SAMPLE_COLS + n) =
                    make_float2(acc[mf][nf][2], acc[mf][nf][3]);
            }
        }
    } else {
        float* epi = (float*)dsm;
        __syncthreads();   // pipeline smem is dead; safe to reuse
#pragma unroll
        for (int mf = 0; mf < 4; mf++) {
#pragma unroll
            for (int nf = 0; nf < 4; nf++) {
                int col = ncol_t + nf * 8;
                int r0 = mrow_t + mf * 16;
                *(float2*)(epi + r0 * EPI_STRIDE + col) =
                    make_float2(acc[mf][nf][0], acc[mf][nf][1]);
                *(float2*)(epi + (r0 + 8) * EPI_STRIDE + col) =
                    make_float2(acc[mf][nf][2], acc[mf][nf][3]);
            }
        }
        __syncthreads();

        const int row = tid >> 1;
        const int cbase = (tid & 1) * 64;
        const int grow = mg * 128 + row;
        const float th = g_thresh[grow];   // includes -MARGIN
        const float* rp = epi + row * EPI_STRIDE + cbase;
        const int nbase = nt * 128 + cbase;
        const int nvalid = N_FEATS - nbase;
#pragma unroll 4
        for (int i4 = 0; i4 < 16; i4++) {
            float4 v = *(const float4*)(rp + i4 * 4);
            if (v.x >= th || v.y >= th || v.z >= th || v.w >= th) {
                int j = i4 * 4;
#pragma unroll
                for (int q = 0; q < 4; q++) {
                    float val = (q == 0) ? v.x : (q == 1) ? v.y : (q == 2) ? v.z : v.w;
                    if (val >= th && j + q < nvalid) {
                        int p = atomicAdd(&g_ccnt[grow], 1);
                        if (p < CAP) g_cii[(size_t)grow * CAP + p] = nbase + j + q;
                    }
                }
            }
        }
    }
}

// ---------------------------------------------------------------------------
// Top-10 machinery (tie-break: lower index)
// ---------------------------------------------------------------------------
static __device__ __forceinline__ bool better(float v, int j, float v2, int j2) {
    return v > v2 || (v == v2 && j < j2);
}
static __device__ __forceinline__ void insert10(float (&tv)[TOPK], int (&ti)[TOPK],
                                                float v, int j) {
    if (!better(v, j, tv[TOPK - 1], ti[TOPK - 1])) return;
    bool b[TOPK];
#pragma unroll
    for (int p = 0; p < TOPK; p++) b[p] = better(v, j, tv[p], ti[p]);
#pragma unroll
    for (int p = TOPK - 1; p >= 1; p--) {
        if (b[p]) {
            if (b[p - 1]) { tv[p] = tv[p - 1]; ti[p] = ti[p - 1]; }
            else          { tv[p] = v;         ti[p] = j;         }
        }
    }
    if (b[0]) { tv[0] = v; ti[0] = j; }
}

#define TK_THREADS 256

static __device__ __forceinline__ void block_merge10(float (&tv)[TOPK], int (&ti)[TOPK],
                                                     float* sv, int* si, float* sv2,
                                                     int* si2, int tid) {
#pragma unroll
    for (int p = 0; p < TOPK; p++) { sv[tid * TOPK + p] = tv[p]; si[tid * TOPK + p] = ti[p]; }
    __syncthreads();
    if (tid < 32) {
#pragma unroll
        for (int p = 0; p < TOPK; p++) { tv[p] = -__int_as_float(0x7f800000); ti[p] = 0x7fffffff; }
        for (int c = tid * 80; c < (tid + 1) * 80; c++)
            insert10(tv, ti, sv[c], si[c]);
#pragma unroll
        for (int p = 0; p < TOPK; p++) { sv2[tid * TOPK + p] = tv[p]; si2[tid * TOPK + p] = ti[p]; }
    }
    __syncthreads();
    if (tid == 0) {
#pragma unroll
        for (int p = 0; p < TOPK; p++) { tv[p] = -__int_as_float(0x7f800000); ti[p] = 0x7fffffff; }
        for (int c = 0; c < 32 * TOPK; c++)
            insert10(tv, ti, sv2[c], si2[c]);
    }
}

// Threshold: 10th-largest of 256 per-thread fmax-maxima (lower bound on the
// sample 10th) minus MARGIN; then push sample-region candidates from registers.
__global__ void __launch_bounds__(TK_THREADS) thresh_kernel() {
    const int row = blockIdx.x;
    const float4* s4 = (const float4*)(g_sample + (size_t)row * SAMPLE_COLS);
    const int tid = threadIdx.x;
    __shared__ float smax[TK_THREADS];
    __shared__ float sv2[32 * TOPK];
    __shared__ float sth;

    float4 v[8];
    float m = -__int_as_float(0x7f800000);
#pragma unroll
    for (int i = 0; i < 8; i++) {
        v[i] = s4[tid + i * TK_THREADS];
        m = fmaxf(m, fmaxf(fmaxf(v[i].x, v[i].y), fmaxf(v[i].z, v[i].w)));
    }
    smax[tid] = m;
    __syncthreads();

    if (tid < 32) {
        float tv[TOPK]; int ti[TOPK];
#pragma unroll
        for (int p = 0; p < TOPK; p++) { tv[p] = -__int_as_float(0x7f800000); ti[p] = 0; }
        for (int c = tid * 8; c < (tid + 1) * 8; c++)
            insert10(tv, ti, smax[c], 0);
#pragma unroll
        for (int p = 0; p < TOPK; p++) sv2[tid * TOPK + p] = tv[p];
    }
    __syncthreads();
    if (tid == 0) {
        float tv[TOPK]; int ti[TOPK];
#pragma unroll
        for (int p = 0; p < TOPK; p++) { tv[p] = -__int_as_float(0x7f800000); ti[p] = 0; }
        for (int c = 0; c < 32 * TOPK; c++)
            insert10(tv, ti, sv2[c], 0);
        float th = tv[TOPK - 1] - MARGIN;
        g_thresh[row] = th;
        sth = th;
    }
    __syncthreads();

    // Push sample-region candidates (values still in registers)
    const float th = sth;
#pragma unroll
    for (int i = 0; i < 8; i++) {
        if (v[i].x >= th || v[i].y >= th || v[i].z >= th || v[i].w >= th) {
            int col = (tid + i * TK_THREADS) * 4;
#pragma unroll
            for (int q = 0; q < 4; q++) {
                float val = (q == 0) ? v[i].x : (q == 1) ? v[i].y : (q == 2) ? v[i].z : v[i].w;
                if (val >= th) {
                    int p = atomicAdd(&g_ccnt[row], 1);
                    if (p < CAP) g_cii[(size_t)row * CAP + p] = col + q;
                }
            }
        }
    }
}

// Rescore candidates exactly in fp32 (2 per warp-iteration), exact top-10,
// one-hot scatter written directly. Overflow rows (cnt > CAP): brute force.
__global__ void __launch_bounds__(TK_THREADS) rescore_select(const float* __restrict__ yp,
                                                             const float* __restrict__ feats,
                                                             const int* __restrict__ y,
                                                             float* __restrict__ out) {
    const int row = blockIdx.x;
    const int tid = threadIdx.x;
    const int lane = tid & 31, w = tid >> 5;
    const int cnt = g_ccnt[row];

    __shared__ float4 a4s[D_DIM / 4];
    __shared__ float  cvs[CAP];
    __shared__ float sv[TK_THREADS * TOPK];
    __shared__ int   si[TK_THREADS * TOPK];
    __shared__ float sv2[32 * TOPK];
    __shared__ int   si2[32 * TOPK];

    if (tid < D_DIM / 4) a4s[tid] = ((const float4*)(yp + (size_t)row * D_DIM))[tid];
    __syncthreads();

    float tv[TOPK]; int ti[TOPK];
#pragma unroll
    for (int p = 0; p < TOPK; p++) { tv[p] = -__int_as_float(0x7f800000); ti[p] = 0x7fffffff; }

    if (cnt <= CAP) {
        const int* ci = g_cii + (size_t)row * CAP;
        int c = w;
        for (; c + 8 < cnt; c += 16) {
            int i0 = ci[c], i1 = ci[c + 8];
            const float4* f0 = (const float4*)(feats + (size_t)i0 * D_DIM);
            const float4* f1 = (const float4*)(feats + (size_t)i1 * D_DIM);
            float s0 = 0.f, s1 = 0.f;
#pragma unroll
            for (int i = 0; i < 4; i++) {
                float4 b0 = f0[i * 32 + lane];
                float4 b1 = f1[i * 32 + lane];
                float4 a = a4s[i * 32 + lane];
                s0 += a.x * b0.x + a.y * b0.y + a.z * b0.z + a.w * b0.w;
                s1 += a.x * b1.x + a.y * b1.y + a.z * b1.z + a.w * b1.w;
            }
#pragma unroll
            for (int o = 16; o; o >>= 1) {
                s0 += __shfl_xor_sync(0xffffffffu, s0, o);
                s1 += __shfl_xor_sync(0xffffffffu, s1, o);
            }
            if (lane == 0) { cvs[c] = s0; cvs[c + 8] = s1; }
        }
        if (c < cnt) {
            int i0 = ci[c];
            const float4* f0 = (const float4*)(feats + (size_t)i0 * D_DIM);
            float s0 = 0.f;
#pragma unroll
            for (int i = 0; i < 4; i++) {
                float4 b0 = f0[i * 32 + lane];
                float4 a = a4s[i * 32 + lane];
                s0 += a.x * b0.x + a.y * b0.y + a.z * b0.z + a.w * b0.w;
            }
#pragma unroll
            for (int o = 16; o; o >>= 1) s0 += __shfl_xor_sync(0xffffffffu, s0, o);
            if (lane == 0) cvs[c] = s0;
        }
        __syncthreads();
        for (int k = tid; k < cnt; k += TK_THREADS)
            insert10(tv, ti, cvs[k], ci[k]);
    } else {
        for (int col = tid; col < N_FEATS; col += TK_THREADS) {
            const float4* f4 = (const float4*)(feats + (size_t)col * D_DIM);
            float s = 0.f;
#pragma unroll 8
            for (int q = 0; q < D_DIM / 4; q++) {
                float4 b = f4[q], a = a4s[q];
                s += a.x * b.x + a.y * b.y + a.z * b.z + a.w * b.w;
            }
            insert10(tv, ti, s, col);
        }
    }
    block_merge10(tv, ti, sv, si, sv2, si2, tid);
    if (tid == 0) {
#pragma unroll
        for (int p = 0; p < TOPK; p++)
            out[(size_t)row * C_CLS + y[ti[p]]] = 1.0f;
    }
}

// ---------------------------------------------------------------------------
extern "C" void kernel_launch(void* const* d_in, const int* in_sizes, int n_in,
                              void* d_out, int out_size) {
    const float* y_pred = (const float*)d_in[0];
    const float* feats  = (const float*)d_in[1];
    const int*   y      = (const int*)d_in[2];
    float* out = (float*)d_out;

    static __nv_bfloat16 *p_fhi = nullptr, *p_ahi = nullptr;
    static float4* p_cnt4 = nullptr;
    if (!p_fhi) {
        cudaGetSymbolAddress((void**)&p_fhi, g_fhi);
        cudaGetSymbolAddress((void**)&p_ahi, g_ahi);
        cudaGetSymbolAddress((void**)&p_cnt4, g_ccnt);
        cudaFuncSetAttribute(gemm_hmma<0>, cudaFuncAttributeMaxDynamicSharedMemorySize,
                             SMEM_TOTAL);
        cudaFuncSetAttribute(gemm_hmma<1>, cudaFuncAttributeMaxDynamicSharedMemorySize,
                             SMEM_TOTAL);
    }

    // cvt(A) also zeroes g_ccnt; cvt(F) also zeroes the output buffer.
    cvt_hi_kernel<<<(B_ROWS * D_DIM / 8 + 255) / 256, 256>>>(
        y_pred, p_ahi, B_ROWS * D_DIM / 8, p_cnt4, B_ROWS / 4);
    cvt_hi_kernel<<<(N_FEATS * D_DIM / 8 + 255) / 256, 256>>>(
        feats, p_fhi, N_FEATS * D_DIM / 8, (float4*)out, out_size / 4);

    // Sample GEMM: first 8192 columns -> g_sample
    gemm_hmma<0><<<dim3(4, SAMPLE_NT), 256, SMEM_TOTAL>>>();
    thresh_kernel<<<B_ROWS, TK_THREADS>>>();   // threshold + sample-region push

    // Main GEMM: remaining 718 tiles only, fused candidate filter
    gemm_hmma<1><<<dim3(4, NT_TOTAL - SAMPLE_NT), 256, SMEM_TOTAL>>>();

    // Exact rescore + direct one-hot scatter
    rescore_select<<<B_ROWS, TK_THREADS>>>(y_pred, feats, y, out);
}